// round 6
// baseline (speedup 1.0000x reference)
#include <cuda_runtime.h>

// ---------------- static scratch (no dynamic allocation allowed) ------------
#define MAXN 50016
#define MAXE 800000

__device__ float g_H1[MAXN * 64];   // layer-1 features x@W1
__device__ float g_as1[MAXN * 4];   // alpha_src layer1 per head (x@v1)
__device__ float g_ad1[MAXN * 4];   // alpha_dst layer1 per head
__device__ float g_X2[MAXN * 64];   // elu(gat1 output) = input to layer2
__device__ float g_H2[MAXN * 32];   // layer-2 features X2@W2
__device__ float g_as2[MAXN];
__device__ float g_ad2[MAXN];
__device__ int   g_deg[MAXN];       // zero at load; re-zeroed by scan each run
__device__ int   g_rowptr[MAXN + 1];
__device__ int   g_wpos[MAXN + 1];
__device__ int   g_csrsrc[MAXE];
__device__ float4 g_w1[MAXE];       // layer-1 edge weights (4 heads), CSR order
__device__ float g_v1[8 * 128];     // [out][k]: 0-3 = W1@a_src1 heads, 4-7 = W1@a_dst1
__device__ float g_v2s[64];         // W2@a_src2
__device__ float g_v2d[64];         // W2@a_dst2

// ---------------- L1: pre (block 0) ⊕ histogram ------------------------------
__global__ void k_pre_hist(const float* __restrict__ W1,
                           const float* __restrict__ a_src1, const float* __restrict__ a_dst1,
                           const float* __restrict__ W2,
                           const float* __restrict__ a_src2, const float* __restrict__ a_dst2,
                           const int* __restrict__ ei, int E) {
    int t = threadIdx.x;
    if (blockIdx.x > 0) {
        int e = (blockIdx.x - 1) * 1024 + t;
        if (e < E) atomicAdd(&g_deg[ei[E + e]], 1);
        return;
    }
    {
        int out = t >> 7, k = t & 127;
        int h = out & 3;
        const float* a = (out < 4) ? a_src1 : a_dst1;
        float sum = 0.f;
#pragma unroll
        for (int c = 0; c < 16; ++c) sum = fmaf(W1[k * 64 + h * 16 + c], a[h * 16 + c], sum);
        g_v1[out * 128 + k] = sum;
    }
    if (t < 64) {
        float s2 = 0.f, d2 = 0.f;
#pragma unroll
        for (int j = 0; j < 32; ++j) {
            float wv = W2[t * 32 + j];
            s2 = fmaf(wv, a_src2[j], s2);
            d2 = fmaf(wv, a_dst2[j], d2);
        }
        g_v2s[t] = s2;
        g_v2d[t] = d2;
    }
}

// ---------------- L2: scan (block 0) ⊕ alphas1 = x @ v1 ---------------------
__global__ void k_scan_asad(const float* __restrict__ x, int N, int nb) {
    int t = threadIdx.x;
    if (blockIdx.x == 0) {
        __shared__ int wsum[32];
        int lane = t & 31, wid = t >> 5;
        if (t == 0) { g_rowptr[0] = 0; g_wpos[0] = 0; }
        int run = 0;
        for (int tile = 0; tile < nb; ++tile) {
            int i = tile * 1024 + t;
            int v = (i < N) ? g_deg[i] : 0;
            if (i < N) g_deg[i] = 0;
            int xx = v;
#pragma unroll
            for (int o = 1; o < 32; o <<= 1) {
                int u = __shfl_up_sync(0xffffffffu, xx, o);
                if (lane >= o) xx += u;
            }
            if (lane == 31) wsum[wid] = xx;
            __syncthreads();
            if (wid == 0) {
                int w = wsum[lane];
#pragma unroll
                for (int o = 1; o < 32; o <<= 1) {
                    int u = __shfl_up_sync(0xffffffffu, w, o);
                    if (lane >= o) w += u;
                }
                wsum[lane] = w;
            }
            __syncthreads();
            int woff = (wid > 0) ? wsum[wid - 1] : 0;
            int total = wsum[31];
            int incl = run + woff + xx;
            if (i < N) { g_rowptr[i + 1] = incl; g_wpos[i + 1] = incl; }
            run += total;
            __syncthreads();
        }
        return;
    }
    int nl = t >> 3, out = t & 7;
    int n = (blockIdx.x - 1) * 128 + nl;
    if (n >= N) return;
    const float4* xr = reinterpret_cast<const float4*>(&x[n * 128]);
    const float4* vr = reinterpret_cast<const float4*>(&g_v1[out * 128]);
    float sum = 0.f;
#pragma unroll
    for (int q = 0; q < 32; ++q) {
        float4 xv = __ldg(&xr[q]);
        float4 vv = vr[q];
        sum += xv.x * vv.x + xv.y * vv.y + xv.z * vv.z + xv.w * vv.w;
    }
    if (out < 4) g_as1[n * 4 + out] = sum;
    else         g_ad1[n * 4 + (out - 4)] = sum;
}

// ---------------- L3: GEMM1 (k-tiled, ~13KB smem) ⊕ CSR fill + w1 ------------
__global__ void k_gemm1_fillw(const float* __restrict__ x, const float* __restrict__ W1,
                              const int* __restrict__ ei, int N, int E, int gemmBlocks) {
    __shared__ float Wsh[16][64];     // 4 KB k-tile of W1
    __shared__ float xs[128][17];     // 8.7 KB

    if (blockIdx.x >= gemmBlocks) {
        int nb = gridDim.x - gemmBlocks;
        int stride = nb * blockDim.x;
        for (int e = (blockIdx.x - gemmBlocks) * blockDim.x + threadIdx.x; e < E; e += stride) {
            int src = ei[e];
            int dst = ei[E + e];
            int p = atomicAdd(&g_wpos[dst], 1);
            g_csrsrc[p] = src;
            float4 as = __ldg(reinterpret_cast<const float4*>(&g_as1[src * 4]));
            float4 ad = __ldg(reinterpret_cast<const float4*>(&g_ad1[dst * 4]));
            float4 w;
            float e0 = as.x + ad.x; w.x = __expf(fmaxf(e0, 0.2f * e0));
            float e1 = as.y + ad.y; w.y = __expf(fmaxf(e1, 0.2f * e1));
            float e2 = as.z + ad.z; w.z = __expf(fmaxf(e2, 0.2f * e2));
            float e3 = as.w + ad.w; w.w = __expf(fmaxf(e3, 0.2f * e3));
            g_w1[p] = w;
        }
        return;
    }

    int t = threadIdx.x;
    int n0 = blockIdx.x * 128;
    int ng = t >> 3;   // node group (4 nodes each)
    int cg = t & 7;    // col group (8 cols each)
    float acc[4][8];
#pragma unroll
    for (int r = 0; r < 4; ++r)
#pragma unroll
        for (int j = 0; j < 8; ++j) acc[r][j] = 0.f;

    for (int kt = 0; kt < 128; kt += 16) {
        __syncthreads();
        // W tile: 16x64 = 1024 floats, 4 per thread
        for (int i = t; i < 16 * 64; i += 256) Wsh[i >> 6][i & 63] = W1[(kt + (i >> 6)) * 64 + (i & 63)];
        // x tile: 128x16 = 2048 floats, 8 per thread
        for (int i = t; i < 128 * 16; i += 256) {
            int n = i >> 4, kk = i & 15;
            int gn = n0 + n;
            xs[n][kk] = (gn < N) ? x[gn * 128 + kt + kk] : 0.f;
        }
        __syncthreads();
#pragma unroll
        for (int kk = 0; kk < 16; ++kk) {
            float wv[8];
#pragma unroll
            for (int j = 0; j < 8; ++j) wv[j] = Wsh[kk][cg * 8 + j];
#pragma unroll
            for (int r = 0; r < 4; ++r) {
                float xv = xs[ng * 4 + r][kk];
#pragma unroll
                for (int j = 0; j < 8; ++j) acc[r][j] = fmaf(xv, wv[j], acc[r][j]);
            }
        }
    }
#pragma unroll
    for (int r = 0; r < 4; ++r) {
        int gn = n0 + ng * 4 + r;
        if (gn < N) {
            float4* dst = reinterpret_cast<float4*>(&g_H1[gn * 64 + cg * 8]);
            dst[0] = make_float4(acc[r][0], acc[r][1], acc[r][2], acc[r][3]);
            dst[1] = make_float4(acc[r][4], acc[r][5], acc[r][6], acc[r][7]);
        }
    }
}

// ---------------- L4: layer-1 aggregation (lean) + as2/ad2 epilogue ----------
__global__ void k_agg1(const float* __restrict__ b1, int N) {
    int gw = (blockIdx.x * blockDim.x + threadIdx.x) >> 5;
    if (gw >= N) return;
    int lane = threadIdx.x & 31;
    int beg = g_rowptr[gw], end = g_rowptr[gw + 1];
    int ch = lane * 2;
    int head = ch >> 4;
    const float* w1f = reinterpret_cast<const float*>(g_w1);

    float s = 0.f, a0 = 0.f, a1 = 0.f;
    int p = beg;
    for (; p + 1 < end; p += 2) {
        int sA = g_csrsrc[p];
        int sB = g_csrsrc[p + 1];
        float wA = __ldg(&w1f[p * 4 + head]);
        float wB = __ldg(&w1f[(p + 1) * 4 + head]);
        float2 hA = *reinterpret_cast<const float2*>(&g_H1[sA * 64 + ch]);
        float2 hB = *reinterpret_cast<const float2*>(&g_H1[sB * 64 + ch]);
        s += wA;
        a0 = fmaf(wA, hA.x, a0);
        a1 = fmaf(wA, hA.y, a1);
        s += wB;
        a0 = fmaf(wB, hB.x, a0);
        a1 = fmaf(wB, hB.y, a1);
    }
    if (p < end) {
        int sA = g_csrsrc[p];
        float wA = __ldg(&w1f[p * 4 + head]);
        float2 hA = *reinterpret_cast<const float2*>(&g_H1[sA * 64 + ch]);
        s += wA;
        a0 = fmaf(wA, hA.x, a0);
        a1 = fmaf(wA, hA.y, a1);
    }
    float inv = 1.f / (s + 1e-16f);
    float o0 = fmaf(a0, inv, b1[ch]);
    float o1 = fmaf(a1, inv, b1[ch + 1]);
    o0 = (o0 > 0.f) ? o0 : expm1f(o0);   // elu
    o1 = (o1 > 0.f) ? o1 : expm1f(o1);
    *reinterpret_cast<float2*>(&g_X2[gw * 64 + ch]) = make_float2(o0, o1);

    // epilogue: as2/ad2 = X2 row . v2  (warp reduction)
    float2 vs = *reinterpret_cast<const float2*>(&g_v2s[ch]);
    float2 vd = *reinterpret_cast<const float2*>(&g_v2d[ch]);
    float ps = o0 * vs.x + o1 * vs.y;
    float pd = o0 * vd.x + o1 * vd.y;
#pragma unroll
    for (int o = 16; o > 0; o >>= 1) {
        ps += __shfl_xor_sync(0xffffffffu, ps, o);
        pd += __shfl_xor_sync(0xffffffffu, pd, o);
    }
    if (lane == 0) { g_as2[gw] = ps; g_ad2[gw] = pd; }
}

// ---------------- L5: GEMM2 (k-tiled, ~11KB smem, 256 threads) ---------------
__global__ void k_gemm2(const float* __restrict__ W2, int N) {
    __shared__ float Wsh[16][32];     // 2 KB k-tile
    __shared__ float xs[128][17];     // 8.7 KB
    int t = threadIdx.x;
    int n0 = blockIdx.x * 128;
    int ng = t >> 2;   // 0..63 (2 nodes each)
    int cg = t & 3;    // 0..3 (8 cols each)
    float acc[2][8];
#pragma unroll
    for (int r = 0; r < 2; ++r)
#pragma unroll
        for (int j = 0; j < 8; ++j) acc[r][j] = 0.f;

    for (int kt = 0; kt < 64; kt += 16) {
        __syncthreads();
        for (int i = t; i < 16 * 32; i += 256) Wsh[i >> 5][i & 31] = W2[(kt + (i >> 5)) * 32 + (i & 31)];
        for (int i = t; i < 128 * 16; i += 256) {
            int n = i >> 4, kk = i & 15;
            int gn = n0 + n;
            xs[n][kk] = (gn < N) ? g_X2[gn * 64 + kt + kk] : 0.f;
        }
        __syncthreads();
#pragma unroll
        for (int kk = 0; kk < 16; ++kk) {
            float wv[8];
#pragma unroll
            for (int j = 0; j < 8; ++j) wv[j] = Wsh[kk][cg * 8 + j];
#pragma unroll
            for (int r = 0; r < 2; ++r) {
                float xv = xs[ng * 2 + r][kk];
#pragma unroll
                for (int j = 0; j < 8; ++j) acc[r][j] = fmaf(xv, wv[j], acc[r][j]);
            }
        }
    }
#pragma unroll
    for (int r = 0; r < 2; ++r) {
        int gn = n0 + ng * 2 + r;
        if (gn < N) {
            float4* dst = reinterpret_cast<float4*>(&g_H2[gn * 32 + cg * 8]);
            dst[0] = make_float4(acc[r][0], acc[r][1], acc[r][2], acc[r][3]);
            dst[1] = make_float4(acc[r][4], acc[r][5], acc[r][6], acc[r][7]);
        }
    }
}

// ---------------- L6: layer-2 aggregation with inline w2 ---------------------
__global__ void k_agg2(const float* __restrict__ b2, float* __restrict__ out, int N) {
    int gw = (blockIdx.x * blockDim.x + threadIdx.x) >> 5;
    if (gw >= N) return;
    int lane = threadIdx.x & 31;
    int beg = g_rowptr[gw], end = g_rowptr[gw + 1];
    float adv = g_ad2[gw];

    float s = 0.f, a = 0.f;
    int p = beg;
    for (; p + 1 < end; p += 2) {
        int sA = g_csrsrc[p];
        int sB = g_csrsrc[p + 1];
        float eA = __ldg(&g_as2[sA]) + adv;
        float eB = __ldg(&g_as2[sB]) + adv;
        float hA = g_H2[sA * 32 + lane];
        float hB = g_H2[sB * 32 + lane];
        float wA = __expf(fmaxf(eA, 0.2f * eA));
        float wB = __expf(fmaxf(eB, 0.2f * eB));
        s += wA;
        a = fmaf(wA, hA, a);
        s += wB;
        a = fmaf(wB, hB, a);
    }
    if (p < end) {
        int sA = g_csrsrc[p];
        float eA = __ldg(&g_as2[sA]) + adv;
        float hA = g_H2[sA * 32 + lane];
        float wA = __expf(fmaxf(eA, 0.2f * eA));
        s += wA;
        a = fmaf(wA, hA, a);
    }
    float inv = 1.f / (s + 1e-16f);
    out[gw * 32 + lane] = fmaf(a, inv, b2[lane]);
}

// ---------------- launch -----------------------------------------------------
extern "C" void kernel_launch(void* const* d_in, const int* in_sizes, int n_in,
                              void* d_out, int out_size) {
    const float* x      = (const float*)d_in[0];
    const int*   ei     = (const int*)  d_in[1];
    const float* W1     = (const float*)d_in[2];
    const float* a_src1 = (const float*)d_in[3];
    const float* a_dst1 = (const float*)d_in[4];
    const float* b1     = (const float*)d_in[5];
    const float* W2     = (const float*)d_in[6];
    const float* a_src2 = (const float*)d_in[7];
    const float* a_dst2 = (const float*)d_in[8];
    const float* b2     = (const float*)d_in[9];

    int N = in_sizes[0] / 128;
    int E = in_sizes[1] / 2;
    int nb = (N + 1023) / 1024;

    int gemm1Blocks = (N + 127) / 128;
    int fillBlocks  = 1184;
    int asadBlocks  = (N + 127) / 128;

    // L1: tiny projections (block 0) + degree histogram
    k_pre_hist<<<1 + (E + 1023) / 1024, 1024>>>(W1, a_src1, a_dst1, W2, a_src2, a_dst2, ei, E);
    // L2: exclusive scan (block 0) + alphas1 = x @ v1
    k_scan_asad<<<1 + asadBlocks, 1024>>>(x, N, nb);
    // L3: GEMM1 overlapped with CSR fill + layer-1 edge weights
    k_gemm1_fillw<<<gemm1Blocks + fillBlocks, 256>>>(x, W1, ei, N, E, gemm1Blocks);
    // L4: layer-1 aggregation (+elu, +as2/ad2)
    k_agg1<<<(N * 32 + 255) / 256, 256>>>(b1, N);
    // L5: GEMM2
    k_gemm2<<<(N + 127) / 128, 256>>>(W2, N);
    // L6: layer-2 aggregation (inline w2)
    k_agg2<<<(N * 32 + 255) / 256, 256>>>(b2, (float*)d_out, N);
}